// round 1
// baseline (speedup 1.0000x reference)
#include <cuda_runtime.h>

#define NC 1024
#define DY 16
#define G  256
#define M  2
#define CH 64

// Axis-separable weight matrices: g_W[axis][m][grid_idx][c]
__device__ float g_W[2][M][G][NC];   // 8 MB scratch

// ---------------------------------------------------------------------------
// Kernel 1: build Wx/Wy (1M exps total)
// ---------------------------------------------------------------------------
__global__ void weights_kernel(const float* __restrict__ xc,
                               const float* __restrict__ lsp) {
    int idx = blockIdx.x * blockDim.x + threadIdx.x;   // 2*2*256*1024 = 1,048,576
    int c = idx & (NC - 1);
    int i = (idx >> 10) & (G - 1);
    int d = (idx >> 18) & 1;
    int m = idx >> 19;
    // lengthscale = 1e-5 + softplus(param)  (param is negative, expf is safe)
    float l = 1e-5f + log1pf(expf(lsp[d]));
    float g = 1.0f + (float)(i - 128) * (1.0f / 64.0f);
    float x = xc[(m * NC + c) * 2 + d];
    float t = (g - x) / l;
    g_W[d][m][i][c] = expf(-0.5f * t * t);
}

// ---------------------------------------------------------------------------
// Kernel 2: fill x_grid_b output (first 262,144 floats of out)
// ---------------------------------------------------------------------------
__global__ void grid_kernel(float* __restrict__ out) {
    int idx = blockIdx.x * blockDim.x + threadIdx.x;   // M*G*G*2 = 262,144
    int d = idx & 1;
    int j = (idx >> 1) & (G - 1);
    int i = (idx >> 9) & (G - 1);
    int v = d ? j : i;
    out[idx] = 1.0f + (float)(v - 128) * (1.0f / 64.0f);
}

// ---------------------------------------------------------------------------
// Kernel 3: fused separable contraction
//   z[m,i,j,k] = sum_c Wx[m,i,c] * Wy[m,j,c] * yc[m,c,k];  k=16 -> density = sum_c w
// CTA: 16x16 (i,j) tile, 256 threads, K-chunks of 64.
// ---------------------------------------------------------------------------
__global__ __launch_bounds__(256)
void setconv_kernel(const float* __restrict__ yc, float* __restrict__ out) {
    __shared__ float  wxs[CH][17];   // [c][i], pad 17: conflict-free STS/LDS
    __shared__ float  wys[CH][17];   // [c][j]
    __shared__ float4 ycs[CH][4];    // [c][k/4]

    const int m  = blockIdx.z;
    const int iT = blockIdx.y;
    const int jT = blockIdx.x;
    const int tid = threadIdx.x;
    const int ti = tid >> 4;         // lanes 0-15 share ti -> wxs read broadcasts
    const int tj = tid & 15;         // consecutive lanes -> consecutive j (coalesced STG)
    const int iBase = iT * 16;
    const int jBase = jT * 16;

    float acc[DY];
    float accD = 0.0f;
#pragma unroll
    for (int k = 0; k < DY; k++) acc[k] = 0.0f;

    const float4* __restrict__ yc4 = (const float4*)yc;

    for (int c0 = 0; c0 < NC; c0 += CH) {
        // --- stage chunk into smem ---
#pragma unroll
        for (int r = 0; r < 4; r++) {
            int idx = tid + r * 256;          // 0..1023
            int cc = idx & (CH - 1);
            int ii = idx >> 6;                // 0..15
            wxs[cc][ii] = g_W[0][m][iBase + ii][c0 + cc];
            wys[cc][ii] = g_W[1][m][jBase + ii][c0 + cc];
        }
        {
            int cc = tid >> 2, q = tid & 3;   // 64*4 = 256 float4 loads
            ycs[cc][q] = yc4[((m * NC + c0 + cc) << 2) + q];
        }
        __syncthreads();

        // --- accumulate ---
#pragma unroll 8
        for (int cc = 0; cc < CH; ++cc) {
            float w = wxs[cc][ti] * wys[cc][tj];
            accD += w;
            float4 y;
            y = ycs[cc][0];
            acc[0]  += w * y.x; acc[1]  += w * y.y; acc[2]  += w * y.z; acc[3]  += w * y.w;
            y = ycs[cc][1];
            acc[4]  += w * y.x; acc[5]  += w * y.y; acc[6]  += w * y.z; acc[7]  += w * y.w;
            y = ycs[cc][2];
            acc[8]  += w * y.x; acc[9]  += w * y.y; acc[10] += w * y.z; acc[11] += w * y.w;
            y = ycs[cc][3];
            acc[12] += w * y.x; acc[13] += w * y.y; acc[14] += w * y.z; acc[15] += w * y.w;
        }
        __syncthreads();
    }

    // --- epilogue: z_grid starts after x_grid_b (M*G*G*2 floats) ---
    const int i = iBase + ti, j = jBase + tj;
    float* zo = out + (size_t)M * G * G * 2 + ((size_t)((m * G + i) * G + j)) * 17;
#pragma unroll
    for (int k = 0; k < DY; k++) zo[k] = acc[k];
    zo[16] = accD;
}

// ---------------------------------------------------------------------------
extern "C" void kernel_launch(void* const* d_in, const int* in_sizes, int n_in,
                              void* d_out, int out_size) {
    const float* xc  = (const float*)d_in[0];  // [2,1024,2]
    const float* yc  = (const float*)d_in[1];  // [2,1024,16]
    // d_in[2] = xt (unused by reference output)
    const float* lsp = (const float*)d_in[3];  // [2]
    float* out = (float*)d_out;

    weights_kernel<<<(M * 2 * G * NC) / 256, 256>>>(xc, lsp);
    grid_kernel<<<(M * G * G * 2) / 256, 256>>>(out);
    dim3 g(G / 16, G / 16, M);                 // (jTile, iTile, m) = 16x16x2
    setconv_kernel<<<g, 256>>>(yc, out);
}

// round 2
// speedup vs baseline: 1.0199x; 1.0199x over previous
#include <cuda_runtime.h>
#include <cstdint>

#define NC 1024
#define DY 16
#define G  256
#define M  2
#define CH 64

typedef unsigned long long u64;

// Axis-separable weight matrices: g_W[axis][m][grid_idx][c]
__device__ float g_W[2][M][G][NC];   // 8 MB scratch

// ---- packed f32x2 helpers (sm_103a) ----
__device__ __forceinline__ u64 pack2(float lo, float hi) {
    u64 r; asm("mov.b64 %0, {%1, %2};" : "=l"(r) : "f"(lo), "f"(hi)); return r;
}
__device__ __forceinline__ void unpack2(float& lo, float& hi, u64 v) {
    asm("mov.b64 {%0, %1}, %2;" : "=f"(lo), "=f"(hi) : "l"(v));
}
__device__ __forceinline__ void ffma2(u64& d, u64 a, u64 b) {
    asm("fma.rn.f32x2 %0, %1, %2, %0;" : "+l"(d) : "l"(a), "l"(b));
}
__device__ __forceinline__ void lds_v2_u64(u64& a, u64& b, uint32_t addr) {
    asm volatile("ld.shared.v2.b64 {%0, %1}, [%2];" : "=l"(a), "=l"(b) : "r"(addr));
}

// ---------------------------------------------------------------------------
// Kernel 1: build Wx/Wy (1M exps total)
// ---------------------------------------------------------------------------
__global__ void weights_kernel(const float* __restrict__ xc,
                               const float* __restrict__ lsp) {
    int idx = blockIdx.x * blockDim.x + threadIdx.x;   // 1,048,576
    int c = idx & (NC - 1);
    int i = (idx >> 10) & (G - 1);
    int d = (idx >> 18) & 1;
    int m = idx >> 19;
    float l = 1e-5f + log1pf(expf(lsp[d]));
    float g = 1.0f + (float)(i - 128) * (1.0f / 64.0f);
    float x = xc[(m * NC + c) * 2 + d];
    float t = (g - x) / l;
    g_W[d][m][i][c] = expf(-0.5f * t * t);
}

// ---------------------------------------------------------------------------
// Kernel 2: fill x_grid_b output (first 262,144 floats of out)
// ---------------------------------------------------------------------------
__global__ void grid_kernel(float* __restrict__ out) {
    int idx = blockIdx.x * blockDim.x + threadIdx.x;   // 262,144
    int d = idx & 1;
    int j = (idx >> 1) & (G - 1);
    int i = (idx >> 9) & (G - 1);
    int v = d ? j : i;
    out[idx] = 1.0f + (float)(v - 128) * (1.0f / 64.0f);
}

// ---------------------------------------------------------------------------
// Kernel 3: fused separable contraction with packed f32x2 FMAs
//   z[m,i,j,k] = sum_c Wx[m,i,c] * Wy[m,j,c] * yc[m,c,k]; k=16 -> density
// CTA: 16x16 (i,j) tile, 256 threads, K-chunks of 64.
// ---------------------------------------------------------------------------
__global__ __launch_bounds__(256)
void setconv_kernel(const float* __restrict__ yc, float* __restrict__ out) {
    __shared__ float  wxs[CH][17];   // [c][i], pad 17
    __shared__ float  wys[CH][17];   // [c][j]
    __shared__ float4 ycs[CH][4];    // [c][k/4] -> read as b64 pairs

    const int m  = blockIdx.z;
    const int iT = blockIdx.y;
    const int jT = blockIdx.x;
    const int tid = threadIdx.x;
    const int ti = tid >> 4;
    const int tj = tid & 15;
    const int iBase = iT * 16;
    const int jBase = jT * 16;

    u64 acc2[8];
#pragma unroll
    for (int q = 0; q < 8; q++) acc2[q] = 0ull;
    float accD = 0.0f;

    const float4* __restrict__ yc4 = (const float4*)yc;
    const uint32_t ycs_addr = (uint32_t)__cvta_generic_to_shared(&ycs[0][0]);

    for (int c0 = 0; c0 < NC; c0 += CH) {
        // --- stage chunk into smem ---
#pragma unroll
        for (int r = 0; r < 4; r++) {
            int idx = tid + r * 256;          // 0..1023
            int cc = idx & (CH - 1);
            int ii = idx >> 6;                // 0..15
            wxs[cc][ii] = g_W[0][m][iBase + ii][c0 + cc];
            wys[cc][ii] = g_W[1][m][jBase + ii][c0 + cc];
        }
        {
            int cc = tid >> 2, q = tid & 3;   // 256 float4 loads
            ycs[cc][q] = yc4[((m * NC + c0 + cc) << 2) + q];
        }
        __syncthreads();

        // --- accumulate (packed) ---
#pragma unroll 4
        for (int cc = 0; cc < CH; ++cc) {
            float w = wxs[cc][ti] * wys[cc][tj];
            accD += w;
            u64 w2 = pack2(w, w);
            u64 y0, y1, y2, y3, y4, y5, y6, y7;
            uint32_t a = ycs_addr + cc * 64;
            lds_v2_u64(y0, y1, a);
            lds_v2_u64(y2, y3, a + 16);
            lds_v2_u64(y4, y5, a + 32);
            lds_v2_u64(y6, y7, a + 48);
            ffma2(acc2[0], w2, y0);
            ffma2(acc2[1], w2, y1);
            ffma2(acc2[2], w2, y2);
            ffma2(acc2[3], w2, y3);
            ffma2(acc2[4], w2, y4);
            ffma2(acc2[5], w2, y5);
            ffma2(acc2[6], w2, y6);
            ffma2(acc2[7], w2, y7);
        }
        __syncthreads();
    }

    // --- epilogue ---
    float acc[DY];
#pragma unroll
    for (int q = 0; q < 8; q++) unpack2(acc[2 * q], acc[2 * q + 1], acc2[q]);

    const int i = iBase + ti, j = jBase + tj;
    float* zo = out + (size_t)M * G * G * 2 + ((size_t)((m * G + i) * G + j)) * 17;
#pragma unroll
    for (int k = 0; k < DY; k++) zo[k] = acc[k];
    zo[16] = accD;
}

// ---------------------------------------------------------------------------
extern "C" void kernel_launch(void* const* d_in, const int* in_sizes, int n_in,
                              void* d_out, int out_size) {
    const float* xc  = (const float*)d_in[0];  // [2,1024,2]
    const float* yc  = (const float*)d_in[1];  // [2,1024,16]
    const float* lsp = (const float*)d_in[3];  // [2]
    float* out = (float*)d_out;

    weights_kernel<<<(M * 2 * G * NC) / 256, 256>>>(xc, lsp);
    grid_kernel<<<(M * G * G * 2) / 256, 256>>>(out);
    dim3 g(G / 16, G / 16, M);
    setconv_kernel<<<g, 256>>>(yc, out);
}

// round 4
// speedup vs baseline: 3.0400x; 2.9808x over previous
#include <cuda_runtime.h>
#include <cstdint>

#define NC 1024
#define DY 16
#define G  256
#define M  2
#define CH 64
#define NT 16          // tiles per dim (G/16)

typedef unsigned long long u64;

// Axis-separable weight matrices: g_W[axis][m][grid_idx][c]
__device__ float g_W[2][M][G][NC];           // 4 MB scratch
__device__ int   g_len[M][NT][NT];           // per-tile relevant-c count
__device__ int   g_list[M][NT][NT][NC];      // per-tile ascending c index list (2 MB)

// ---- packed f32x2 helpers (sm_103a) ----
__device__ __forceinline__ u64 pack2(float lo, float hi) {
    u64 r; asm("mov.b64 %0, {%1, %2};" : "=l"(r) : "f"(lo), "f"(hi)); return r;
}
__device__ __forceinline__ void unpack2(float& lo, float& hi, u64 v) {
    asm("mov.b64 {%0, %1}, %2;" : "=f"(lo), "=f"(hi) : "l"(v));
}
__device__ __forceinline__ void ffma2(u64& d, u64 a, u64 b) {
    asm("fma.rn.f32x2 %0, %1, %2, %0;" : "+l"(d) : "l"(a), "l"(b));
}
__device__ __forceinline__ void lds_v2_u64(u64& a, u64& b, uint32_t addr) {
    asm volatile("ld.shared.v2.b64 {%0, %1}, [%2];" : "=l"(a), "=l"(b) : "r"(addr));
}

// ---------------------------------------------------------------------------
// Kernel 1: build Wx/Wy (1M exps)
// ---------------------------------------------------------------------------
__global__ void weights_kernel(const float* __restrict__ xc,
                               const float* __restrict__ lsp) {
    int idx = blockIdx.x * blockDim.x + threadIdx.x;   // 1,048,576
    int c = idx & (NC - 1);
    int i = (idx >> 10) & (G - 1);
    int d = (idx >> 18) & 1;
    int m = idx >> 19;
    float l = 1e-5f + log1pf(expf(lsp[d]));
    float rl = 1.0f / l;
    float g = 1.0f + (float)(i - 128) * (1.0f / 64.0f);
    float x = xc[(m * NC + c) * 2 + d];
    float t = (g - x) * rl;
    g_W[d][m][i][c] = expf(-0.5f * t * t);
}

// ---------------------------------------------------------------------------
// Kernel 2: fill x_grid_b output (first 262,144 floats)
// ---------------------------------------------------------------------------
__global__ void grid_kernel(float* __restrict__ out) {
    int idx = blockIdx.x * blockDim.x + threadIdx.x;   // 262,144
    int d = idx & 1;
    int j = (idx >> 1) & (G - 1);
    int i = (idx >> 9) & (G - 1);
    int v = d ? j : i;
    out[idx] = 1.0f + (float)(v - 128) * (1.0f / 64.0f);
}

// ---------------------------------------------------------------------------
// Kernel 3: per-tile c-list compaction. One warp per (m, iT, jT) tile.
// Deterministic ordered compaction via ballot+popc (ascending c).
// Keep c if min-distance from tile box, scaled by lengthscales, gives
// weight >= ~1e-6  (dist2_scaled <= 2*ln(1e6) = 27.63).
// ---------------------------------------------------------------------------
__global__ void compact_kernel(const float* __restrict__ xc,
                               const float* __restrict__ lsp) {
    int warp = (blockIdx.x * blockDim.x + threadIdx.x) >> 5;
    int lane = threadIdx.x & 31;
    if (warp >= M * NT * NT) return;
    int jT = warp & (NT - 1);
    int iT = (warp >> 4) & (NT - 1);
    int m  = warp >> 8;

    float rlx = 1.0f / (1e-5f + log1pf(expf(lsp[0])));
    float rly = 1.0f / (1e-5f + log1pf(expf(lsp[1])));
    float x0 = 1.0f + (float)(iT * 16 - 128) * (1.0f / 64.0f);
    float x1 = x0 + 15.0f / 64.0f;
    float y0 = 1.0f + (float)(jT * 16 - 128) * (1.0f / 64.0f);
    float y1 = y0 + 15.0f / 64.0f;
    const float thr = 27.63f;

    int count = 0;
    int* lst = g_list[m][iT][jT];
    for (int c0 = 0; c0 < NC; c0 += 32) {
        int c = c0 + lane;
        float cx = xc[(m * NC + c) * 2 + 0];
        float cy = xc[(m * NC + c) * 2 + 1];
        float dx = fmaxf(fmaxf(x0 - cx, cx - x1), 0.0f) * rlx;
        float dy = fmaxf(fmaxf(y0 - cy, cy - y1), 0.0f) * rly;
        bool keep = (dx * dx + dy * dy) <= thr;
        unsigned mask = __ballot_sync(0xffffffffu, keep);
        int off = __popc(mask & ((1u << lane) - 1u));
        if (keep) lst[count + off] = c;
        count += __popc(mask);
    }
    if (lane == 0) g_len[m][iT][jT] = count;
}

// ---------------------------------------------------------------------------
// Kernel 4: fused separable contraction over the compacted c-list.
//   z[m,i,j,k] = sum_{c in list} Wx[m,i,c] * Wy[m,j,c] * yc[m,c,k]
// CTA: 16x16 (i,j) tile, 256 threads, chunks of 64 list entries.
// ---------------------------------------------------------------------------
__global__ __launch_bounds__(256)
void setconv_kernel(const float* __restrict__ yc, float* __restrict__ out) {
    __shared__ float  wxs[CH][17];
    __shared__ float  wys[CH][17];
    __shared__ float4 ycs[CH][4];

    const int m  = blockIdx.z;
    const int iT = blockIdx.y;
    const int jT = blockIdx.x;
    const int tid = threadIdx.x;
    const int ti = tid >> 4;
    const int tj = tid & 15;
    const int iBase = iT * 16;
    const int jBase = jT * 16;

    u64 acc2[8];
#pragma unroll
    for (int q = 0; q < 8; q++) acc2[q] = 0ull;
    float accD = 0.0f;

    const int len = g_len[m][iT][jT];
    const int* __restrict__ lst = g_list[m][iT][jT];
    const float4* __restrict__ yc4 = (const float4*)yc;
    const uint32_t ycs_addr = (uint32_t)__cvta_generic_to_shared(&ycs[0][0]);

    for (int c0 = 0; c0 < len; c0 += CH) {
        // --- stage chunk (gathered via list) ---
#pragma unroll
        for (int r = 0; r < 4; r++) {
            int idx = tid + r * 256;
            int cc = idx & (CH - 1);
            int ii = idx >> 6;
            int cpos = c0 + cc;
            bool valid = cpos < len;
            int cidx = valid ? lst[cpos] : 0;
            wxs[cc][ii] = valid ? g_W[0][m][iBase + ii][cidx] : 0.0f;
            wys[cc][ii] = valid ? g_W[1][m][jBase + ii][cidx] : 0.0f;
        }
        {
            int cc = tid >> 2, q = tid & 3;
            int cpos = c0 + cc;
            int cidx = (cpos < len) ? lst[cpos] : 0;
            ycs[cc][q] = yc4[((m * NC + cidx) << 2) + q];
        }
        __syncthreads();

        // --- accumulate (packed f32x2) ---
#pragma unroll 4
        for (int cc = 0; cc < CH; ++cc) {
            float w = wxs[cc][ti] * wys[cc][tj];
            accD += w;
            u64 w2 = pack2(w, w);
            u64 y0, y1, y2, y3, y4, y5, y6, y7;
            uint32_t a = ycs_addr + cc * 64;
            lds_v2_u64(y0, y1, a);
            lds_v2_u64(y2, y3, a + 16);
            lds_v2_u64(y4, y5, a + 32);
            lds_v2_u64(y6, y7, a + 48);
            ffma2(acc2[0], w2, y0);
            ffma2(acc2[1], w2, y1);
            ffma2(acc2[2], w2, y2);
            ffma2(acc2[3], w2, y3);
            ffma2(acc2[4], w2, y4);
            ffma2(acc2[5], w2, y5);
            ffma2(acc2[6], w2, y6);
            ffma2(acc2[7], w2, y7);
        }
        __syncthreads();
    }

    // --- epilogue ---
    float acc[DY];
#pragma unroll
    for (int q = 0; q < 8; q++) unpack2(acc[2 * q], acc[2 * q + 1], acc2[q]);

    const int i = iBase + ti, j = jBase + tj;
    float* zo = out + (size_t)M * G * G * 2 + ((size_t)((m * G + i) * G + j)) * 17;
#pragma unroll
    for (int k = 0; k < DY; k++) zo[k] = acc[k];
    zo[16] = accD;
}

// ---------------------------------------------------------------------------
extern "C" void kernel_launch(void* const* d_in, const int* in_sizes, int n_in,
                              void* d_out, int out_size) {
    const float* xc  = (const float*)d_in[0];  // [2,1024,2]
    const float* yc  = (const float*)d_in[1];  // [2,1024,16]
    const float* lsp = (const float*)d_in[3];  // [2]
    float* out = (float*)d_out;

    weights_kernel<<<(M * 2 * G * NC) / 256, 256>>>(xc, lsp);
    compact_kernel<<<(M * NT * NT * 32 + 255) / 256, 256>>>(xc, lsp);
    grid_kernel<<<(M * G * G * 2) / 256, 256>>>(out);
    dim3 g(NT, NT, M);
    setconv_kernel<<<g, 256>>>(yc, out);
}